// round 15
// baseline (speedup 1.0000x reference)
#include <cuda_runtime.h>
#include <cuda_fp16.h>
#include <math.h>
#include <stdint.h>

// ---------------------------------------------------------------------------
// Problem constants
// ---------------------------------------------------------------------------
#define BATCH   4
#define TSEQ    1024
#define DFEAT   1024
#define NQV     2048
#define MROWS   (BATCH * TSEQ)   // 4096
#define C0      21
#define C1      41
#define NLOGPAD 256

// ---------------------------------------------------------------------------
// Scratch (no cudaMalloc allowed)
// ---------------------------------------------------------------------------
__device__ __half g_qh    [(size_t)MROWS * DFEAT];    // query fp16
__device__ __half g_wqvh  [(size_t)DFEAT * NQV];      // W_qv  [1024,2048] fp16 (natural)
__device__ __half g_wouth [(size_t)DFEAT * DFEAT];    // W_out [1024,1024] fp16 (natural)
__device__ __half g_w2h   [(size_t)DFEAT * NLOGPAD];  // packed W2 [1024,256] fp16 (natural)
__device__ __half g_qrelu [(size_t)MROWS * DFEAT];    // relu(q) fp16
__device__ __half g_vh    [(size_t)MROWS * DFEAT];    // v fp16
__device__ float  g_logits[(size_t)MROWS * NLOGPAD];
__device__ __half g_xh    [(size_t)MROWS * DFEAT];    // mixed output fp16

// ---------------------------------------------------------------------------
// Helpers
// ---------------------------------------------------------------------------
__device__ __forceinline__ uint32_t smem_u32(const void* p) {
    uint32_t a;
    asm("{ .reg .u64 t; cvta.to.shared.u64 t, %1; cvt.u32.u64 %0, t; }" : "=r"(a) : "l"(p));
    return a;
}
__device__ __forceinline__ void cp_async16(uint32_t dst, const void* src) {
    asm volatile("cp.async.cg.shared.global [%0], [%1], 16;" :: "r"(dst), "l"(src));
}
__device__ __forceinline__ void cp_async16z(uint32_t dst, const void* src, int valid) {
    int sz = valid ? 16 : 0;
    asm volatile("cp.async.cg.shared.global [%0], [%1], 16, %2;"
                 :: "r"(dst), "l"(src), "r"(sz));
}
__device__ __forceinline__ void cp_commit() {
    asm volatile("cp.async.commit_group;" ::: "memory");
}
__device__ __forceinline__ void ldsm4(uint32_t* r, uint32_t addr) {
    asm volatile("ldmatrix.sync.aligned.m8n8.x4.shared.b16 {%0,%1,%2,%3}, [%4];"
        : "=r"(r[0]), "=r"(r[1]), "=r"(r[2]), "=r"(r[3]) : "r"(addr));
}
__device__ __forceinline__ void ldsm4t(uint32_t* r, uint32_t addr) {
    asm volatile("ldmatrix.sync.aligned.m8n8.x4.trans.shared.b16 {%0,%1,%2,%3}, [%4];"
        : "=r"(r[0]), "=r"(r[1]), "=r"(r[2]), "=r"(r[3]) : "r"(addr));
}
__device__ __forceinline__ void mma_f16(float* c, const uint32_t* a, const uint32_t* b) {
    asm volatile("mma.sync.aligned.m16n8k16.row.col.f32.f16.f16.f32 "
        "{%0,%1,%2,%3}, {%4,%5,%6,%7}, {%8,%9}, {%0,%1,%2,%3};"
        : "+f"(c[0]), "+f"(c[1]), "+f"(c[2]), "+f"(c[3])
        : "r"(a[0]), "r"(a[1]), "r"(a[2]), "r"(a[3]), "r"(b[0]), "r"(b[1]));
}

// ---------------------------------------------------------------------------
// Prep: ONE kernel. query/W_qv/W_out f32->f16 + W2 pack.
// ---------------------------------------------------------------------------
#define CVT_Q4  (MROWS * DFEAT / 4)
#define CVT_W4  (DFEAT * NQV / 4)
#define CVT_O4  (DFEAT * DFEAT / 4)
#define CVT_N4  (CVT_Q4 + CVT_W4 + CVT_O4)
#define W2_G4   (DFEAT * NLOGPAD / 4)
#define PREP_TOT (CVT_N4 + W2_G4)

__global__ void prep_kernel(const float4* __restrict__ q,
                            const float4* __restrict__ wqv,
                            const float4* __restrict__ wout,
                            const float* __restrict__ w20,
                            const float* __restrict__ w21) {
    int i = blockIdx.x * 256 + threadIdx.x;
    if (i >= PREP_TOT) return;
    if (i < CVT_N4) {
        const float4* src; __half* dst; int off;
        if (i < CVT_Q4)               { src = q;    dst = g_qh;    off = i; }
        else if (i < CVT_Q4 + CVT_W4) { src = wqv;  dst = g_wqvh;  off = i - CVT_Q4; }
        else                          { src = wout; dst = g_wouth; off = i - CVT_Q4 - CVT_W4; }
        float4 v = src[off];
        __half2 h0 = __floats2half2_rn(v.x, v.y);
        __half2 h1 = __floats2half2_rn(v.z, v.w);
        *(uint2*)(dst + (size_t)off * 4) = make_uint2(*(uint32_t*)&h0, *(uint32_t*)&h1);
    } else {
        int g = i - CVT_N4;
        int k = g >> 6;
        int n4 = (g & 63) * 4;
        float v0, v1, v2, v3;
        if (n4 < 84) {
            const float* s = w20 + k * 84 + n4;
            v0 = s[0]; v1 = s[1]; v2 = s[2]; v3 = s[3];
        } else if (n4 < 248) {
            const float* s = w21 + k * 164 + (n4 - 84);
            v0 = s[0]; v1 = s[1]; v2 = s[2]; v3 = s[3];
        } else {
            v0 = v1 = v2 = v3 = 0.f;
        }
        __half2 h0 = __floats2half2_rn(v0, v1);
        __half2 h1 = __floats2half2_rn(v2, v3);
        *(uint2*)(g_w2h + (size_t)k * NLOGPAD + n4) =
            make_uint2(*(uint32_t*)&h0, *(uint32_t*)&h1);
    }
}

// ---------------------------------------------------------------------------
// fp16 mma.sync GEMM: C[M,N] = A[M,K] @ B[K,N], fp32 accumulate.
// MODE 0: fp32 to Cq. MODE 1 (qv split): col<DFEAT -> relu fp16 Cq;
//         col>=DFEAT -> fp16 Cv (v).
// ---------------------------------------------------------------------------
#define BK 64
#define NSTAGE 3

template <int TBM, int TWM, int MODE>
__global__ __launch_bounds__(256, 2)
void hgemm_kernel(const __half* __restrict__ A, int lda,
                  const __half* __restrict__ B, int ldb,
                  void* __restrict__ Cq, void* __restrict__ Cv,
                  int ldc, int K) {
    constexpr int ATB = TBM * BK * 2;
    constexpr int BTB = BK * 128 * 2;
    constexpr int STB = ATB + BTB;
    constexpr int MT  = TWM / 16;
    constexpr int WM_CNT = TBM / TWM;

    extern __shared__ char smem[];
    const uint32_t sb = smem_u32(smem);
    const int tid = threadIdx.x;
    const int lane = tid & 31, warp = tid >> 5;
    const int wm = (warp & (WM_CNT - 1)) * TWM;
    const int wn = (warp / WM_CNT) * 32;
    const int mBase = blockIdx.y * TBM;
    const int nBase = blockIdx.x * 128;
    const int lrow = lane & 7, mat = lane >> 3;

    const __half* Abase = A + (size_t)mBase * lda;
    const __half* Bbase = B + nBase;
    const int NIT = K / BK;

    float acc[MT][4][4];
#pragma unroll
    for (int i = 0; i < MT; i++)
#pragma unroll
        for (int j = 0; j < 4; j++)
#pragma unroll
            for (int l = 0; l < 4; l++) acc[i][j][l] = 0.f;

    auto load_tile = [&](uint32_t stageBase, const __half* Ag, const __half* Bg) {
#pragma unroll
        for (int i = 0; i < TBM / 32; i++) {
            int cid = tid + i * 256;
            int r = cid >> 3, ch = cid & 7;
            uint32_t dst = stageBase + r * 128 + ((ch ^ (r & 7)) << 4);
            cp_async16(dst, Ag + (size_t)r * lda + ch * 8);
        }
        uint32_t bB = stageBase + ATB;
#pragma unroll
        for (int i = 0; i < 4; i++) {
            int cid = tid + i * 256;
            int r = cid >> 4, ch = cid & 15;
            uint32_t dst = bB + r * 256 + ((ch ^ (r & 7)) << 4);
            cp_async16(dst, Bg + (size_t)r * ldb + ch * 8);
        }
    };

    load_tile(sb, Abase, Bbase); cp_commit();
    load_tile(sb + STB, Abase + BK, Bbase + (size_t)BK * ldb); cp_commit();

    int arow[MT];
#pragma unroll
    for (int mt = 0; mt < MT; mt++) arow[mt] = wm + mt * 16 + ((mat & 1) << 3) + lrow;
    const int achunk = (mat >> 1);
    const int cbase = (wn >> 3) + (mat >> 1);

    for (int it = 0; it < NIT; it++) {
        int s = it - (it / 3) * 3;
        asm volatile("cp.async.wait_group 1;" ::: "memory");
        __syncthreads();

        uint32_t aTile = sb + s * STB;
        uint32_t bTile = aTile + ATB;

#pragma unroll
        for (int kk = 0; kk < 4; kk++) {
            uint32_t af[MT][4], bf[4][2];
#pragma unroll
            for (int mt = 0; mt < MT; mt++) {
                int ch = 2 * kk + achunk;
                uint32_t addr = aTile + arow[mt] * 128 + ((ch ^ (arow[mt] & 7)) << 4);
                ldsm4(af[mt], addr);
            }
            {
                int kb = kk * 16 + ((mat & 1) << 3) + lrow;
                uint32_t rowAddr = bTile + kb * 256;
                int kx = kb & 7;
                uint32_t a0 = rowAddr + (((cbase)     ^ kx) << 4);
                uint32_t a1 = rowAddr + (((cbase + 2) ^ kx) << 4);
                uint32_t r[4];
                ldsm4t(r, a0);
                bf[0][0] = r[0]; bf[0][1] = r[1]; bf[1][0] = r[2]; bf[1][1] = r[3];
                ldsm4t(r, a1);
                bf[2][0] = r[0]; bf[2][1] = r[1]; bf[3][0] = r[2]; bf[3][1] = r[3];
            }
#pragma unroll
            for (int mt = 0; mt < MT; mt++)
#pragma unroll
                for (int nt = 0; nt < 4; nt++)
                    mma_f16(acc[mt][nt], af[mt], bf[nt]);
        }

        if (it + 2 < NIT) {
            int sw = (it + 2) - ((it + 2) / 3) * 3;
            load_tile(sb + sw * STB, Abase + (it + 2) * BK,
                      Bbase + (size_t)(it + 2) * BK * ldb);
        }
        cp_commit();
    }

    const int g = lane >> 2, tig = lane & 3;
#pragma unroll
    for (int mt = 0; mt < MT; mt++) {
#pragma unroll
        for (int nt = 0; nt < 4; nt++) {
            int row = mBase + wm + mt * 16 + g;
            int col = nBase + wn + nt * 8 + tig * 2;
            if (MODE == 0) {
                float* C = (float*)Cq;
                *(float2*)(C + (size_t)row * ldc + col) =
                    make_float2(acc[mt][nt][0], acc[mt][nt][1]);
                *(float2*)(C + (size_t)(row + 8) * ldc + col) =
                    make_float2(acc[mt][nt][2], acc[mt][nt][3]);
            } else {
                if (col < DFEAT) {
                    __half* Q = (__half*)Cq;
                    __half2 h0 = __floats2half2_rn(fmaxf(acc[mt][nt][0], 0.f),
                                                   fmaxf(acc[mt][nt][1], 0.f));
                    __half2 h1 = __floats2half2_rn(fmaxf(acc[mt][nt][2], 0.f),
                                                   fmaxf(acc[mt][nt][3], 0.f));
                    *(__half2*)(Q + (size_t)row * DFEAT + col) = h0;
                    *(__half2*)(Q + (size_t)(row + 8) * DFEAT + col) = h1;
                } else {
                    __half* V = (__half*)Cv;
                    int vc = col - DFEAT;
                    __half2 h0 = __floats2half2_rn(acc[mt][nt][0], acc[mt][nt][1]);
                    __half2 h1 = __floats2half2_rn(acc[mt][nt][2], acc[mt][nt][3]);
                    *(__half2*)(V + (size_t)row * DFEAT + vc) = h0;
                    *(__half2*)(V + (size_t)(row + 8) * DFEAT + vc) = h1;
                }
            }
        }
    }
}

// ---------------------------------------------------------------------------
// Fused attn v5: t-tile 128 x D-slice 128 per block (grid 256, 2 CTA/SM).
//   O[128,128] = W[128,176] @ V[176,128]   (fp16 MMA, fp32 accum)
// Halo overhead 18.75% (was 63% at t=32/64 D-split or 2x softmax at t64xD256).
// V rows 256B swizzled (validated algebra); W band 368B rows (368*k mod 128
// cycles through {112,96,80,64,48,32,16} -> conflict-free ldsm4).
// cp.async V overlaps W-zero + warp-parallel softmax.
// Per-warp k-range clipped to its band: rows [wm, wm+63] touch k in
// [wm, wm+104) -> 7 k16-steps starting at wm.
// ---------------------------------------------------------------------------
#define ATT_T     128
#define ATT_VROWS 176            // 168 valid (128+40 halo) + 8 pad
#define ATT_VBYTES (ATT_VROWS * 256)          // 45056
#define ATT_WSTRIDE 184                        // halves (368B rows)
#define ATT_WBYTES (ATT_T * ATT_WSTRIDE * 2)   // 47104
#define ATT_SMEM (ATT_VBYTES + ATT_WBYTES)     // 92160

__global__ __launch_bounds__(256, 2)
void attn_tc_kernel(const float* __restrict__ sweights) {
    extern __shared__ char sm[];
    __half* vs = (__half*)sm;
    __half* Wb = (__half*)(sm + ATT_VBYTES);
    const uint32_t vsB = smem_u32(vs);
    const uint32_t wsB = smem_u32(Wb);

    const int t0 = blockIdx.x * ATT_T;
    const int by = blockIdx.y;        // 0..7 : D-slice (head = by>>1)
    const int b  = blockIdx.z;
    const int h  = by >> 1;
    const int coff = by * 128;
    const int tid = threadIdx.x;
    const int lane = tid & 31, warp = tid >> 5;

    // ---- (1) V tile via cp.async: 176 rows x 16 chunks(16B) = 2816 ops ----
#pragma unroll
    for (int i = 0; i < 11; i++) {
        int cid = tid + i * 256;
        int row = cid >> 4, ch = cid & 15;
        int gt = t0 - 20 + row;
        int valid = (row < 168) && (gt >= 0) && (gt < TSEQ);
        int gts = valid ? gt : 0;
        cp_async16z(vsB + row * 256 + ((ch ^ (row & 7)) << 4),
                    g_vh + (size_t)(b * TSEQ + gts) * DFEAT + coff + ch * 8, valid);
    }
    cp_commit();

    // ---- (2) zero W band matrix: 47104B = 2944 uint4 ----
    for (int idx = tid; idx < ATT_WBYTES / 16; idx += 256)
        ((uint4*)Wb)[idx] = make_uint4(0u, 0u, 0u, 0u);
    __syncthreads();

    // ---- (3) warp-parallel softmax: warp w handles rows w, w+8, ..., w+120 ----
    {
        float w0 = sweights[0], w1 = sweights[1];
        float mmw = fmaxf(w0, w1);
        float ew0 = __expf(w0 - mmw), ew1 = __expf(w1 - mmw);
        float sden = 1.f / (ew0 + ew1);

#pragma unroll
        for (int i = 0; i < 16; i++) {
            int tl = warp + i * 8;
            const float* lp = g_logits + (size_t)(b * TSEQ + t0 + tl) * NLOGPAD;
            float l0  = (lane < C0) ? lp[h * 21 + lane] : -1e30f;
            float l1a = lp[84 + h * 41 + lane];
            float l1b = (lane + 32 < C1) ? lp[84 + h * 41 + lane + 32] : -1e30f;

            float m0 = l0, m1 = fmaxf(l1a, l1b);
#pragma unroll
            for (int off = 16; off >= 1; off >>= 1) {
                m0 = fmaxf(m0, __shfl_xor_sync(0xFFFFFFFFu, m0, off));
                m1 = fmaxf(m1, __shfl_xor_sync(0xFFFFFFFFu, m1, off));
            }
            float e0  = (lane < C0) ? __expf(l0 - m0) : 0.f;
            float e1a = __expf(l1a - m1);
            float e1b = (lane + 32 < C1) ? __expf(l1b - m1) : 0.f;
            float s0 = e0, s1 = e1a + e1b;
#pragma unroll
            for (int off = 16; off >= 1; off >>= 1) {
                s0 += __shfl_xor_sync(0xFFFFFFFFu, s0, off);
                s1 += __shfl_xor_sync(0xFFFFFFFFu, s1, off);
            }
            float inv0 = ew0 * sden / s0;
            float inv1 = ew1 * sden / s1;

            float c0term = __shfl_up_sync(0xFFFFFFFFu, e0 * inv0, 10);
            float wa = e1a * inv1 + ((lane >= 10 && lane < 31) ? c0term : 0.f);

            // band write: W[tl][tl + c], c in [0,41)
            __half* wr = Wb + tl * ATT_WSTRIDE + tl;
            wr[lane] = __float2half_rn(wa);
            if (lane + 32 < C1) wr[lane + 32] = __float2half_rn(e1b * inv1);
        }
    }

    // ---- (4) V arrival + visibility ----
    asm volatile("cp.async.wait_group 0;" ::: "memory");
    __syncthreads();

    // ---- (5) MMA: 8 warps = 2(m64) x 4(n32); k clipped: 7 k16 steps from wm ----
    const int lrow = lane & 7, mat = lane >> 3;
    const int wm = (warp & 1) * 64;
    const int wn = (warp >> 1) * 32;
    const int kc0 = wm >> 3;          // base chunk of this warp's k-range

    float acc[4][4][4];
#pragma unroll
    for (int mt = 0; mt < 4; mt++)
#pragma unroll
        for (int nt = 0; nt < 4; nt++)
#pragma unroll
            for (int l = 0; l < 4; l++) acc[mt][nt][l] = 0.f;

#pragma unroll
    for (int ks = 0; ks < 7; ks++) {
        uint32_t af[4][4];
#pragma unroll
        for (int mt = 0; mt < 4; mt++) {
            int row = wm + mt * 16 + ((mat & 1) << 3) + lrow;
            int ch = kc0 + 2 * ks + (mat >> 1);
            ldsm4(af[mt], wsB + row * (ATT_WSTRIDE * 2) + (ch << 4));
        }
        uint32_t bf[4][2];
        {
            int kb = wm + ks * 16 + ((mat & 1) << 3) + lrow;   // absolute V row
            int kx = kb & 7;
            int cb0 = (wn >> 3) + (mat >> 1);
            uint32_t rowAddr = vsB + kb * 256;
            uint32_t r[4];
            ldsm4t(r, rowAddr + ((cb0 ^ kx) << 4));
            bf[0][0] = r[0]; bf[0][1] = r[1]; bf[1][0] = r[2]; bf[1][1] = r[3];
            ldsm4t(r, rowAddr + (((cb0 + 2) ^ kx) << 4));
            bf[2][0] = r[0]; bf[2][1] = r[1]; bf[3][0] = r[2]; bf[3][1] = r[3];
        }
#pragma unroll
        for (int mt = 0; mt < 4; mt++)
#pragma unroll
            for (int nt = 0; nt < 4; nt++)
                mma_f16(acc[mt][nt], af[mt], bf[nt]);
    }

    // ---- epilogue: fragment-mapped fp16 store ----
    const int g = lane >> 2, tig = lane & 3;
#pragma unroll
    for (int mt = 0; mt < 4; mt++) {
#pragma unroll
        for (int nt = 0; nt < 4; nt++) {
            int row = wm + mt * 16 + g;
            int col = coff + wn + nt * 8 + tig * 2;
            __half2 h0 = __floats2half2_rn(acc[mt][nt][0], acc[mt][nt][1]);
            __half2 h1 = __floats2half2_rn(acc[mt][nt][2], acc[mt][nt][3]);
            *(__half2*)(g_xh + (size_t)(b * TSEQ + t0 + row) * DFEAT + col) = h0;
            *(__half2*)(g_xh + (size_t)(b * TSEQ + t0 + row + 8) * DFEAT + col) = h1;
        }
    }
}

// ---------------------------------------------------------------------------
// Launch
// ---------------------------------------------------------------------------
extern "C" void kernel_launch(void* const* d_in, const int* in_sizes, int n_in,
                              void* d_out, int out_size) {
    const float* query    = (const float*)d_in[0];
    // d_in[1]=key, d_in[2]=value: unused by reference
    const float* W_qv     = (const float*)d_in[3];
    const float* W2_0     = (const float*)d_in[4];
    const float* W2_1     = (const float*)d_in[5];
    const float* sweights = (const float*)d_in[6];
    const float* W_out    = (const float*)d_in[7];
    float* out = (float*)d_out;

    constexpr int SMEM_128 = NSTAGE * (128 * BK * 2 + BK * 128 * 2);  // 98304
    constexpr int SMEM_32  = NSTAGE * (32 * BK * 2 + BK * 128 * 2);   // 61440
    cudaFuncSetAttribute(hgemm_kernel<128, 64, 1>,
                         cudaFuncAttributeMaxDynamicSharedMemorySize, SMEM_128);
    cudaFuncSetAttribute(hgemm_kernel<128, 64, 0>,
                         cudaFuncAttributeMaxDynamicSharedMemorySize, SMEM_128);
    cudaFuncSetAttribute(hgemm_kernel<32, 16, 0>,
                         cudaFuncAttributeMaxDynamicSharedMemorySize, SMEM_32);
    cudaFuncSetAttribute(attn_tc_kernel,
                         cudaFuncAttributeMaxDynamicSharedMemorySize, ATT_SMEM);

    void *qh_p = nullptr, *wqvh_p = nullptr, *wouth_p = nullptr, *w2h_p = nullptr;
    void *qrelu_p = nullptr, *vh_p = nullptr, *logits_p = nullptr, *xh_p = nullptr;
    cudaGetSymbolAddress(&qh_p, g_qh);
    cudaGetSymbolAddress(&wqvh_p, g_wqvh);
    cudaGetSymbolAddress(&wouth_p, g_wouth);
    cudaGetSymbolAddress(&w2h_p, g_w2h);
    cudaGetSymbolAddress(&qrelu_p, g_qrelu);
    cudaGetSymbolAddress(&vh_p, g_vh);
    cudaGetSymbolAddress(&logits_p, g_logits);
    cudaGetSymbolAddress(&xh_p, g_xh);

    // 1) prep
    prep_kernel<<<(PREP_TOT + 255) / 256, 256>>>(
        (const float4*)query, (const float4*)W_qv, (const float4*)W_out, W2_0, W2_1);

    // 2) qv = query @ W_qv : q half -> relu fp16; v half -> fp16
    hgemm_kernel<128, 64, 1><<<dim3(NQV / 128, MROWS / 128), 256, SMEM_128>>>(
        (const __half*)qh_p, DFEAT, (const __half*)wqvh_p, NQV,
        qrelu_p, vh_p, 0, DFEAT);

    // 3) logits = relu(q) @ W2
    hgemm_kernel<32, 16, 0><<<dim3(NLOGPAD / 128, MROWS / 32), 256, SMEM_32>>>(
        (const __half*)qrelu_p, DFEAT, (const __half*)w2h_p, NLOGPAD,
        logits_p, nullptr, NLOGPAD, DFEAT);

    // 4) fused softmax + tensor-core window apply -> g_xh (fp16)
    attn_tc_kernel<<<dim3(TSEQ / ATT_T, 8, BATCH), 256, ATT_SMEM>>>(sweights);

    // 5) out = x @ W_out
    hgemm_kernel<128, 64, 0><<<dim3(DFEAT / 128, MROWS / 128), 256, SMEM_128>>>(
        (const __half*)xh_p, DFEAT, (const __half*)wouth_p, DFEAT,
        out, nullptr, DFEAT, DFEAT);
}

// round 16
// speedup vs baseline: 1.0721x; 1.0721x over previous
#include <cuda_runtime.h>
#include <cuda_fp16.h>
#include <math.h>
#include <stdint.h>

// ---------------------------------------------------------------------------
// Problem constants
// ---------------------------------------------------------------------------
#define BATCH   4
#define TSEQ    1024
#define DFEAT   1024
#define NQV     2048
#define MROWS   (BATCH * TSEQ)   // 4096
#define C0      21
#define C1      41
#define NLOGPAD 256

// ---------------------------------------------------------------------------
// Scratch (no cudaMalloc allowed)
// ---------------------------------------------------------------------------
__device__ __half g_qh    [(size_t)MROWS * DFEAT];    // query fp16
__device__ __half g_wqvh  [(size_t)DFEAT * NQV];      // W_qv  [1024,2048] fp16 (natural)
__device__ __half g_wouth [(size_t)DFEAT * DFEAT];    // W_out [1024,1024] fp16 (natural)
__device__ __half g_w2h   [(size_t)DFEAT * NLOGPAD];  // packed W2 [1024,256] fp16 (natural)
__device__ __half g_qrelu [(size_t)MROWS * DFEAT];    // relu(q) fp16
__device__ __half g_vh    [(size_t)MROWS * DFEAT];    // v fp16
__device__ float  g_logits[(size_t)MROWS * NLOGPAD];
__device__ __half g_xh    [(size_t)MROWS * DFEAT];    // mixed output fp16

// ---------------------------------------------------------------------------
// Helpers
// ---------------------------------------------------------------------------
__device__ __forceinline__ uint32_t smem_u32(const void* p) {
    uint32_t a;
    asm("{ .reg .u64 t; cvta.to.shared.u64 t, %1; cvt.u32.u64 %0, t; }" : "=r"(a) : "l"(p));
    return a;
}
__device__ __forceinline__ void cp_async16(uint32_t dst, const void* src) {
    asm volatile("cp.async.cg.shared.global [%0], [%1], 16;" :: "r"(dst), "l"(src));
}
__device__ __forceinline__ void cp_async16z(uint32_t dst, const void* src, int valid) {
    int sz = valid ? 16 : 0;
    asm volatile("cp.async.cg.shared.global [%0], [%1], 16, %2;"
                 :: "r"(dst), "l"(src), "r"(sz));
}
__device__ __forceinline__ void cp_commit() {
    asm volatile("cp.async.commit_group;" ::: "memory");
}
__device__ __forceinline__ void ldsm4(uint32_t* r, uint32_t addr) {
    asm volatile("ldmatrix.sync.aligned.m8n8.x4.shared.b16 {%0,%1,%2,%3}, [%4];"
        : "=r"(r[0]), "=r"(r[1]), "=r"(r[2]), "=r"(r[3]) : "r"(addr));
}
__device__ __forceinline__ void ldsm4t(uint32_t* r, uint32_t addr) {
    asm volatile("ldmatrix.sync.aligned.m8n8.x4.trans.shared.b16 {%0,%1,%2,%3}, [%4];"
        : "=r"(r[0]), "=r"(r[1]), "=r"(r[2]), "=r"(r[3]) : "r"(addr));
}
__device__ __forceinline__ void mma_f16(float* c, const uint32_t* a, const uint32_t* b) {
    asm volatile("mma.sync.aligned.m16n8k16.row.col.f32.f16.f16.f32 "
        "{%0,%1,%2,%3}, {%4,%5,%6,%7}, {%8,%9}, {%0,%1,%2,%3};"
        : "+f"(c[0]), "+f"(c[1]), "+f"(c[2]), "+f"(c[3])
        : "r"(a[0]), "r"(a[1]), "r"(a[2]), "r"(a[3]), "r"(b[0]), "r"(b[1]));
}

// ---------------------------------------------------------------------------
// Prep: ONE kernel. query/W_qv/W_out f32->f16 + W2 pack.
// ---------------------------------------------------------------------------
#define CVT_Q4  (MROWS * DFEAT / 4)
#define CVT_W4  (DFEAT * NQV / 4)
#define CVT_O4  (DFEAT * DFEAT / 4)
#define CVT_N4  (CVT_Q4 + CVT_W4 + CVT_O4)
#define W2_G4   (DFEAT * NLOGPAD / 4)
#define PREP_TOT (CVT_N4 + W2_G4)

__global__ void prep_kernel(const float4* __restrict__ q,
                            const float4* __restrict__ wqv,
                            const float4* __restrict__ wout,
                            const float* __restrict__ w20,
                            const float* __restrict__ w21) {
    int i = blockIdx.x * 256 + threadIdx.x;
    if (i >= PREP_TOT) return;
    if (i < CVT_N4) {
        const float4* src; __half* dst; int off;
        if (i < CVT_Q4)               { src = q;    dst = g_qh;    off = i; }
        else if (i < CVT_Q4 + CVT_W4) { src = wqv;  dst = g_wqvh;  off = i - CVT_Q4; }
        else                          { src = wout; dst = g_wouth; off = i - CVT_Q4 - CVT_W4; }
        float4 v = src[off];
        __half2 h0 = __floats2half2_rn(v.x, v.y);
        __half2 h1 = __floats2half2_rn(v.z, v.w);
        *(uint2*)(dst + (size_t)off * 4) = make_uint2(*(uint32_t*)&h0, *(uint32_t*)&h1);
    } else {
        int g = i - CVT_N4;
        int k = g >> 6;
        int n4 = (g & 63) * 4;
        float v0, v1, v2, v3;
        if (n4 < 84) {
            const float* s = w20 + k * 84 + n4;
            v0 = s[0]; v1 = s[1]; v2 = s[2]; v3 = s[3];
        } else if (n4 < 248) {
            const float* s = w21 + k * 164 + (n4 - 84);
            v0 = s[0]; v1 = s[1]; v2 = s[2]; v3 = s[3];
        } else {
            v0 = v1 = v2 = v3 = 0.f;
        }
        __half2 h0 = __floats2half2_rn(v0, v1);
        __half2 h1 = __floats2half2_rn(v2, v3);
        *(uint2*)(g_w2h + (size_t)k * NLOGPAD + n4) =
            make_uint2(*(uint32_t*)&h0, *(uint32_t*)&h1);
    }
}

// ---------------------------------------------------------------------------
// fp16 mma.sync GEMM: C[M,N] = A[M,K] @ B[K,N], fp32 accumulate.
// MODE 0: fp32 to Cq. MODE 1 (qv split): col<DFEAT -> relu fp16 Cq;
//         col>=DFEAT -> fp16 Cv (v).
// ---------------------------------------------------------------------------
#define BK 64
#define NSTAGE 3

template <int TBM, int TWM, int MODE>
__global__ __launch_bounds__(256, 2)
void hgemm_kernel(const __half* __restrict__ A, int lda,
                  const __half* __restrict__ B, int ldb,
                  void* __restrict__ Cq, void* __restrict__ Cv,
                  int ldc, int K) {
    constexpr int ATB = TBM * BK * 2;
    constexpr int BTB = BK * 128 * 2;
    constexpr int STB = ATB + BTB;
    constexpr int MT  = TWM / 16;
    constexpr int WM_CNT = TBM / TWM;

    extern __shared__ char smem[];
    const uint32_t sb = smem_u32(smem);
    const int tid = threadIdx.x;
    const int lane = tid & 31, warp = tid >> 5;
    const int wm = (warp & (WM_CNT - 1)) * TWM;
    const int wn = (warp / WM_CNT) * 32;
    const int mBase = blockIdx.y * TBM;
    const int nBase = blockIdx.x * 128;
    const int lrow = lane & 7, mat = lane >> 3;

    const __half* Abase = A + (size_t)mBase * lda;
    const __half* Bbase = B + nBase;
    const int NIT = K / BK;

    float acc[MT][4][4];
#pragma unroll
    for (int i = 0; i < MT; i++)
#pragma unroll
        for (int j = 0; j < 4; j++)
#pragma unroll
            for (int l = 0; l < 4; l++) acc[i][j][l] = 0.f;

    auto load_tile = [&](uint32_t stageBase, const __half* Ag, const __half* Bg) {
#pragma unroll
        for (int i = 0; i < TBM / 32; i++) {
            int cid = tid + i * 256;
            int r = cid >> 3, ch = cid & 7;
            uint32_t dst = stageBase + r * 128 + ((ch ^ (r & 7)) << 4);
            cp_async16(dst, Ag + (size_t)r * lda + ch * 8);
        }
        uint32_t bB = stageBase + ATB;
#pragma unroll
        for (int i = 0; i < 4; i++) {
            int cid = tid + i * 256;
            int r = cid >> 4, ch = cid & 15;
            uint32_t dst = bB + r * 256 + ((ch ^ (r & 7)) << 4);
            cp_async16(dst, Bg + (size_t)r * ldb + ch * 8);
        }
    };

    load_tile(sb, Abase, Bbase); cp_commit();
    load_tile(sb + STB, Abase + BK, Bbase + (size_t)BK * ldb); cp_commit();

    int arow[MT];
#pragma unroll
    for (int mt = 0; mt < MT; mt++) arow[mt] = wm + mt * 16 + ((mat & 1) << 3) + lrow;
    const int achunk = (mat >> 1);
    const int cbase = (wn >> 3) + (mat >> 1);

    for (int it = 0; it < NIT; it++) {
        int s = it - (it / 3) * 3;
        asm volatile("cp.async.wait_group 1;" ::: "memory");
        __syncthreads();

        uint32_t aTile = sb + s * STB;
        uint32_t bTile = aTile + ATB;

#pragma unroll
        for (int kk = 0; kk < 4; kk++) {
            uint32_t af[MT][4], bf[4][2];
#pragma unroll
            for (int mt = 0; mt < MT; mt++) {
                int ch = 2 * kk + achunk;
                uint32_t addr = aTile + arow[mt] * 128 + ((ch ^ (arow[mt] & 7)) << 4);
                ldsm4(af[mt], addr);
            }
            {
                int kb = kk * 16 + ((mat & 1) << 3) + lrow;
                uint32_t rowAddr = bTile + kb * 256;
                int kx = kb & 7;
                uint32_t a0 = rowAddr + (((cbase)     ^ kx) << 4);
                uint32_t a1 = rowAddr + (((cbase + 2) ^ kx) << 4);
                uint32_t r[4];
                ldsm4t(r, a0);
                bf[0][0] = r[0]; bf[0][1] = r[1]; bf[1][0] = r[2]; bf[1][1] = r[3];
                ldsm4t(r, a1);
                bf[2][0] = r[0]; bf[2][1] = r[1]; bf[3][0] = r[2]; bf[3][1] = r[3];
            }
#pragma unroll
            for (int mt = 0; mt < MT; mt++)
#pragma unroll
                for (int nt = 0; nt < 4; nt++)
                    mma_f16(acc[mt][nt], af[mt], bf[nt]);
        }

        if (it + 2 < NIT) {
            int sw = (it + 2) - ((it + 2) / 3) * 3;
            load_tile(sb + sw * STB, Abase + (it + 2) * BK,
                      Bbase + (size_t)(it + 2) * BK * ldb);
        }
        cp_commit();
    }

    const int g = lane >> 2, tig = lane & 3;
#pragma unroll
    for (int mt = 0; mt < MT; mt++) {
#pragma unroll
        for (int nt = 0; nt < 4; nt++) {
            int row = mBase + wm + mt * 16 + g;
            int col = nBase + wn + nt * 8 + tig * 2;
            if (MODE == 0) {
                float* C = (float*)Cq;
                *(float2*)(C + (size_t)row * ldc + col) =
                    make_float2(acc[mt][nt][0], acc[mt][nt][1]);
                *(float2*)(C + (size_t)(row + 8) * ldc + col) =
                    make_float2(acc[mt][nt][2], acc[mt][nt][3]);
            } else {
                if (col < DFEAT) {
                    __half* Q = (__half*)Cq;
                    __half2 h0 = __floats2half2_rn(fmaxf(acc[mt][nt][0], 0.f),
                                                   fmaxf(acc[mt][nt][1], 0.f));
                    __half2 h1 = __floats2half2_rn(fmaxf(acc[mt][nt][2], 0.f),
                                                   fmaxf(acc[mt][nt][3], 0.f));
                    *(__half2*)(Q + (size_t)row * DFEAT + col) = h0;
                    *(__half2*)(Q + (size_t)(row + 8) * DFEAT + col) = h1;
                } else {
                    __half* V = (__half*)Cv;
                    int vc = col - DFEAT;
                    __half2 h0 = __floats2half2_rn(acc[mt][nt][0], acc[mt][nt][1]);
                    __half2 h1 = __floats2half2_rn(acc[mt][nt][2], acc[mt][nt][3]);
                    *(__half2*)(V + (size_t)row * DFEAT + vc) = h0;
                    *(__half2*)(V + (size_t)(row + 8) * DFEAT + vc) = h1;
                }
            }
        }
    }
}

// ---------------------------------------------------------------------------
// Fused attn (round-13 structure + latency fixes):
// t-tile 64 x full head (D=256), grid 256, 2 CTA/SM.
//   O[64,256] = W[64,112] @ V[112,256]   (fp16 MMA, fp32 accum)
// Fix 1: softmax logit loads hoisted (24 LDGs in flight before reductions).
// Fix 2: epilogue staged through smem (528B padded rows, conflict-free STS)
//        then fully-coalesced STG.128, reusing the V buffer after sync.
// ---------------------------------------------------------------------------
#define ATT_VROWS 112            // 104 valid + 8 pad
#define ATT_VBYTES (ATT_VROWS * 512)          // 57344
#define ATT_WSTRIDE 120                        // halves (240B rows)
#define ATT_WBYTES (64 * ATT_WSTRIDE * 2)      // 15360
#define ATT_SMEM (ATT_VBYTES + ATT_WBYTES)     // 72704
#define OST_ROWB 528                           // output staging row stride (bytes)

__global__ __launch_bounds__(256, 2)
void attn_tc_kernel(const float* __restrict__ sweights) {
    extern __shared__ char sm[];
    __half* vs = (__half*)sm;
    __half* Wb = (__half*)(sm + ATT_VBYTES);
    const uint32_t vsB = smem_u32(vs);
    const uint32_t wsB = smem_u32(Wb);

    const int t0 = blockIdx.x * 64;
    const int h  = blockIdx.y;        // head 0..3
    const int b  = blockIdx.z;
    const int coff = h * 256;
    const int tid = threadIdx.x;
    const int lane = tid & 31, warp = tid >> 5;

    // ---- (1) V tile via cp.async (in flight during softmax) ----
#pragma unroll
    for (int i = 0; i < 14; i++) {
        int cid = tid + i * 256;
        int row = cid >> 5, ch = cid & 31;
        int gt = t0 - 20 + row;
        int valid = (row < 104) && (gt >= 0) && (gt < TSEQ);
        int gts = valid ? gt : 0;
        cp_async16z(vsB + row * 512 + ((ch ^ (row & 7)) << 4),
                    g_vh + (size_t)(b * TSEQ + gts) * DFEAT + coff + ch * 8, valid);
    }
    cp_commit();

    // ---- (2) zero W band matrix ----
    for (int idx = tid; idx < ATT_WBYTES / 16; idx += 256)
        ((uint4*)Wb)[idx] = make_uint4(0u, 0u, 0u, 0u);
    __syncthreads();

    // ---- (3) warp-parallel softmax, loads hoisted ----
    {
        float L0[8], L1a[8], L1b[8];
#pragma unroll
        for (int i = 0; i < 8; i++) {
            int tl = warp + i * 8;
            const float* lp = g_logits + (size_t)(b * TSEQ + t0 + tl) * NLOGPAD;
            L0[i]  = (lane < C0) ? lp[h * 21 + lane] : -1e30f;
            L1a[i] = lp[84 + h * 41 + lane];
            L1b[i] = (lane + 32 < C1) ? lp[84 + h * 41 + lane + 32] : -1e30f;
        }

        float w0 = sweights[0], w1 = sweights[1];
        float mmw = fmaxf(w0, w1);
        float ew0 = __expf(w0 - mmw), ew1 = __expf(w1 - mmw);
        float sden = 1.f / (ew0 + ew1);

#pragma unroll
        for (int i = 0; i < 8; i++) {
            int tl = warp + i * 8;
            float m0 = L0[i], m1 = fmaxf(L1a[i], L1b[i]);
#pragma unroll
            for (int off = 16; off >= 1; off >>= 1) {
                m0 = fmaxf(m0, __shfl_xor_sync(0xFFFFFFFFu, m0, off));
                m1 = fmaxf(m1, __shfl_xor_sync(0xFFFFFFFFu, m1, off));
            }
            float e0  = (lane < C0) ? __expf(L0[i] - m0) : 0.f;
            float e1a = __expf(L1a[i] - m1);
            float e1b = (lane + 32 < C1) ? __expf(L1b[i] - m1) : 0.f;
            float s0 = e0, s1 = e1a + e1b;
#pragma unroll
            for (int off = 16; off >= 1; off >>= 1) {
                s0 += __shfl_xor_sync(0xFFFFFFFFu, s0, off);
                s1 += __shfl_xor_sync(0xFFFFFFFFu, s1, off);
            }
            float inv0 = ew0 * sden / s0;
            float inv1 = ew1 * sden / s1;

            float c0term = __shfl_up_sync(0xFFFFFFFFu, e0 * inv0, 10);
            float wa = e1a * inv1 + ((lane >= 10 && lane < 31) ? c0term : 0.f);

            __half* wr = Wb + tl * ATT_WSTRIDE + tl;
            wr[lane] = __float2half_rn(wa);
            if (lane + 32 < C1) wr[lane + 32] = __float2half_rn(e1b * inv1);
        }
    }

    // ---- (4) V arrival + visibility ----
    asm volatile("cp.async.wait_group 0;" ::: "memory");
    __syncthreads();

    // ---- (5) MMA: 8 warps, each m32 x n64; k clipped to band [wm, wm+72] ----
    const int lrow = lane & 7, mat = lane >> 3;
    const int wm = (warp & 1) * 32;
    const int wn = (warp >> 1) * 64;
    const int kstart = wm >> 4;       // 0 or 2

    float acc[2][8][4];
#pragma unroll
    for (int mt = 0; mt < 2; mt++)
#pragma unroll
        for (int nt = 0; nt < 8; nt++)
#pragma unroll
            for (int l = 0; l < 4; l++) acc[mt][nt][l] = 0.f;

#pragma unroll
    for (int ks = 0; ks < 5; ks++) {
        const int kk = kstart + ks;
        uint32_t af[2][4];
#pragma unroll
        for (int mt = 0; mt < 2; mt++) {
            int row = wm + mt * 16 + ((mat & 1) << 3) + lrow;
            ldsm4(af[mt], wsB + row * (ATT_WSTRIDE * 2) + ((2 * kk + (mat >> 1)) << 4));
        }
        uint32_t bf[8][2];
        {
            int kb = kk * 16 + ((mat & 1) << 3) + lrow;
            int kx = kb & 7;
            int cb0 = (wn >> 3) + (mat >> 1);
            uint32_t rowAddr = vsB + kb * 512;
#pragma unroll
            for (int j = 0; j < 4; j++) {
                uint32_t r[4];
                ldsm4t(r, rowAddr + (((cb0 + 2 * j) ^ kx) << 4));
                bf[2 * j][0] = r[0];     bf[2 * j][1] = r[1];
                bf[2 * j + 1][0] = r[2]; bf[2 * j + 1][1] = r[3];
            }
        }
#pragma unroll
        for (int mt = 0; mt < 2; mt++)
#pragma unroll
            for (int nt = 0; nt < 8; nt++)
                mma_f16(acc[mt][nt], af[mt], bf[nt]);
    }

    // ---- (6) epilogue: stage in smem (reuse V buffer), then coalesced STG ----
    __syncthreads();    // all warps done reading vs
    {
        const int g = lane >> 2, tig = lane & 3;
#pragma unroll
        for (int mt = 0; mt < 2; mt++) {
#pragma unroll
            for (int nt = 0; nt < 8; nt++) {
                int row = wm + mt * 16 + g;
                int col = wn + nt * 8 + tig * 2;     // 0..255 within head
                __half2 h0 = __floats2half2_rn(acc[mt][nt][0], acc[mt][nt][1]);
                __half2 h1 = __floats2half2_rn(acc[mt][nt][2], acc[mt][nt][3]);
                *(__half2*)((char*)vs + row * OST_ROWB + col * 2) = h0;
                *(__half2*)((char*)vs + (row + 8) * OST_ROWB + col * 2) = h1;
            }
        }
    }
    __syncthreads();
    // copy out: 64 rows x 32 chunks(16B), coalesced
#pragma unroll
    for (int i = 0; i < 8; i++) {
        int cid = tid + i * 256;
        int r = cid >> 5, ch = cid & 31;
        uint4 val = *(const uint4*)((char*)vs + r * OST_ROWB + ch * 16);
        *(uint4*)(g_xh + (size_t)(b * TSEQ + t0 + r) * DFEAT + coff + ch * 8) = val;
    }
}

// ---------------------------------------------------------------------------
// Launch
// ---------------------------------------------------------------------------
extern "C" void kernel_launch(void* const* d_in, const int* in_sizes, int n_in,
                              void* d_out, int out_size) {
    const float* query    = (const float*)d_in[0];
    // d_in[1]=key, d_in[2]=value: unused by reference
    const float* W_qv     = (const float*)d_in[3];
    const float* W2_0     = (const float*)d_in[4];
    const float* W2_1     = (const float*)d_in[5];
    const float* sweights = (const float*)d_in[6];
    const float* W_out    = (const float*)d_in[7];
    float* out = (float*)d_out;

    constexpr int SMEM_128 = NSTAGE * (128 * BK * 2 + BK * 128 * 2);  // 98304
    constexpr int SMEM_32  = NSTAGE * (32 * BK * 2 + BK * 128 * 2);   // 61440
    cudaFuncSetAttribute(hgemm_kernel<128, 64, 1>,
                         cudaFuncAttributeMaxDynamicSharedMemorySize, SMEM_128);
    cudaFuncSetAttribute(hgemm_kernel<128, 64, 0>,
                         cudaFuncAttributeMaxDynamicSharedMemorySize, SMEM_128);
    cudaFuncSetAttribute(hgemm_kernel<32, 16, 0>,
                         cudaFuncAttributeMaxDynamicSharedMemorySize, SMEM_32);
    cudaFuncSetAttribute(attn_tc_kernel,
                         cudaFuncAttributeMaxDynamicSharedMemorySize, ATT_SMEM);

    void *qh_p = nullptr, *wqvh_p = nullptr, *wouth_p = nullptr, *w2h_p = nullptr;
    void *qrelu_p = nullptr, *vh_p = nullptr, *logits_p = nullptr, *xh_p = nullptr;
    cudaGetSymbolAddress(&qh_p, g_qh);
    cudaGetSymbolAddress(&wqvh_p, g_wqvh);
    cudaGetSymbolAddress(&wouth_p, g_wouth);
    cudaGetSymbolAddress(&w2h_p, g_w2h);
    cudaGetSymbolAddress(&qrelu_p, g_qrelu);
    cudaGetSymbolAddress(&vh_p, g_vh);
    cudaGetSymbolAddress(&logits_p, g_logits);
    cudaGetSymbolAddress(&xh_p, g_xh);

    // 1) prep
    prep_kernel<<<(PREP_TOT + 255) / 256, 256>>>(
        (const float4*)query, (const float4*)W_qv, (const float4*)W_out, W2_0, W2_1);

    // 2) qv = query @ W_qv : q half -> relu fp16; v half -> fp16
    hgemm_kernel<128, 64, 1><<<dim3(NQV / 128, MROWS / 128), 256, SMEM_128>>>(
        (const __half*)qh_p, DFEAT, (const __half*)wqvh_p, NQV,
        qrelu_p, vh_p, 0, DFEAT);

    // 3) logits = relu(q) @ W2
    hgemm_kernel<32, 16, 0><<<dim3(NLOGPAD / 128, MROWS / 32), 256, SMEM_32>>>(
        (const __half*)qrelu_p, DFEAT, (const __half*)w2h_p, NLOGPAD,
        logits_p, nullptr, NLOGPAD, DFEAT);

    // 4) fused softmax + tensor-core window apply -> g_xh (fp16)
    attn_tc_kernel<<<dim3(TSEQ / 64, 4, BATCH), 256, ATT_SMEM>>>(sweights);

    // 5) out = x @ W_out
    hgemm_kernel<128, 64, 0><<<dim3(DFEAT / 128, MROWS / 128), 256, SMEM_128>>>(
        (const __half*)xh_p, DFEAT, (const __half*)wouth_p, DFEAT,
        out, nullptr, DFEAT, DFEAT);
}